// round 3
// baseline (speedup 1.0000x reference)
#include <cuda_runtime.h>

// GRU -> LSTM -> FC fused recurrent kernel.
// B=1024 sequences, T=1024 steps, H=18.
// One warp per batch element. Weights live in registers (each lane owns
// 2 GRU rows and 3 LSTM rows of W_ih/W_hh). State vectors (x_t, h_gru,
// h_lstm) are exchanged through per-warp shared memory with broadcast
// reads. Packed f32x2 FMA halves the FMA instruction count.

#define Hh 18
#define Tt 1024
#define Bb 1024

typedef unsigned long long ull;

__device__ __forceinline__ void fma2(ull &d, ull a, ull b) {
    asm("fma.rn.f32x2 %0, %1, %2, %0;" : "+l"(d) : "l"(a), "l"(b));
}
__device__ __forceinline__ float hadd2(ull v) {
    float lo, hi;
    asm("mov.b64 {%0,%1}, %2;" : "=f"(lo), "=f"(hi) : "l"(v));
    return lo + hi;
}
// sigmoid(x) = 1/(1+e^-x); safe at extremes (inf handled by rcp -> 0)
__device__ __forceinline__ float sigf(float x) {
    return __fdividef(1.f, 1.f + __expf(-x));
}
// tanh(x) = 1 - 2/(1+e^{2x}); safe at extremes
__device__ __forceinline__ float tanhf_(float x) {
    return 1.f - __fdividef(2.f, 1.f + __expf(2.f * x));
}

__global__ __launch_bounds__(32) void gru_lstm_fused(
    const float* __restrict__ x,
    const float* __restrict__ gWih, const float* __restrict__ gWhh,
    const float* __restrict__ gbih, const float* __restrict__ gbhh,
    const float* __restrict__ lWih, const float* __restrict__ lWhh,
    const float* __restrict__ lbih, const float* __restrict__ lbhh,
    const float* __restrict__ fcW, const float* __restrict__ fcb,
    float* __restrict__ out)
{
    const int j = threadIdx.x;   // lane
    const int b = blockIdx.x;    // batch element

    // per-warp (per-block) state in shared memory
    __shared__ __align__(16) float sx[Hh];    // x_t
    __shared__ __align__(16) float shg[Hh];   // GRU hidden
    __shared__ __align__(16) float shl[Hh];   // LSTM hidden
    __shared__ __align__(16) float sxi[54];   // GRU input-proj rows (incl bih)
    __shared__ __align__(16) float shh[54];   // GRU hidden-proj rows (incl bhh)
    __shared__ __align__(16) float sl[72];    // LSTM pre-activation rows

    // ---- load weights into registers (one-time) ----
    // GRU: lane j (<27) owns rows 2j, 2j+1 of gWih/gWhh  (rows are 18 floats = 9 f32x2)
    ull wgx[2][9], wgh[2][9];
    float bgx[2], bgh[2];
    if (j < 27) {
        #pragma unroll
        for (int r = 0; r < 2; r++) {
            const int row = 2 * j + r;
            const ull* pi = (const ull*)(gWih + row * Hh);
            const ull* ph = (const ull*)(gWhh + row * Hh);
            #pragma unroll
            for (int k = 0; k < 9; k++) { wgx[r][k] = pi[k]; wgh[r][k] = ph[k]; }
            bgx[r] = gbih[row];
            bgh[r] = gbhh[row];
        }
    }
    // LSTM: lane j (<24) owns rows 3j, 3j+1, 3j+2 of lWih/lWhh
    ull wlx[3][9], wlh[3][9];
    float bl[3];
    if (j < 24) {
        #pragma unroll
        for (int r = 0; r < 3; r++) {
            const int row = 3 * j + r;
            const ull* pi = (const ull*)(lWih + row * Hh);
            const ull* ph = (const ull*)(lWhh + row * Hh);
            #pragma unroll
            for (int k = 0; k < 9; k++) { wlx[r][k] = pi[k]; wlh[r][k] = ph[k]; }
            bl[r] = lbih[row] + lbhh[row];   // always summed in LSTM pre-activation
        }
    }
    const float fw = (j < Hh) ? fcW[j] : 0.f;
    const float fb = fcb[0];

    // ---- init state ----
    if (j < Hh) { shg[j] = 0.f; shl[j] = 0.f; }
    float c  = 0.f;   // LSTM cell (lane j holds element j, j<18)
    float hg = 0.f;   // GRU hidden register copy (lane j holds element j)

    const float* xb = x + (size_t)b * Tt * Hh;
    float*       ob = out + (size_t)b * Tt;

    float xv = (j < Hh) ? xb[j] : 0.f;   // prefetch x_0
    float ov[4];                          // output staging (lane 0)
    __syncwarp();

    #pragma unroll 1
    for (int t = 0; t < Tt; t++) {
        // publish x_t, prefetch x_{t+1} (LDG latency hidden behind the step)
        if (j < Hh) sx[j] = xv;
        float xnx = 0.f;
        if (j < Hh && t + 1 < Tt) xnx = xb[(size_t)(t + 1) * Hh + j];
        __syncwarp();   // A

        // ---- GRU matvecs: rows 2j, 2j+1 ----
        if (j < 27) {
            ull a0 = 0ULL, a1 = 0ULL, h0 = 0ULL, h1 = 0ULL;
            const ull* px = (const ull*)sx;
            const ull* ph = (const ull*)shg;
            #pragma unroll
            for (int k = 0; k < 9; k++) {
                const ull xk = px[k], hk = ph[k];
                fma2(a0, wgx[0][k], xk); fma2(h0, wgh[0][k], hk);
                fma2(a1, wgx[1][k], xk); fma2(h1, wgh[1][k], hk);
            }
            sxi[2 * j]     = hadd2(a0) + bgx[0];
            sxi[2 * j + 1] = hadd2(a1) + bgx[1];
            shh[2 * j]     = hadd2(h0) + bgh[0];
            shh[2 * j + 1] = hadd2(h1) + bgh[1];
        }
        __syncwarp();   // B

        // ---- GRU gates (lane j = element j) ----
        if (j < Hh) {
            const float r = sigf(sxi[j]      + shh[j]);
            const float z = sigf(sxi[18 + j] + shh[18 + j]);
            const float n = tanhf_(fmaf(r, shh[36 + j], sxi[36 + j]));
            hg = fmaf(z, hg - n, n);            // (1-z)*n + z*h
            shg[j] = hg;
        }
        __syncwarp();   // C

        // ---- LSTM matvecs: rows 3j..3j+2 (g = GRU output just computed) ----
        if (j < 24) {
            ull s0 = 0ULL, s1 = 0ULL, s2 = 0ULL;
            const ull* pg = (const ull*)shg;
            const ull* ph = (const ull*)shl;
            #pragma unroll
            for (int k = 0; k < 9; k++) {
                const ull gk = pg[k], hk = ph[k];
                fma2(s0, wlx[0][k], gk); fma2(s0, wlh[0][k], hk);
                fma2(s1, wlx[1][k], gk); fma2(s1, wlh[1][k], hk);
                fma2(s2, wlx[2][k], gk); fma2(s2, wlh[2][k], hk);
            }
            sl[3 * j]     = hadd2(s0) + bl[0];
            sl[3 * j + 1] = hadd2(s1) + bl[1];
            sl[3 * j + 2] = hadd2(s2) + bl[2];
        }
        __syncwarp();   // D

        // ---- LSTM gates + fc contribution ----
        float v = 0.f;
        if (j < Hh) {
            const float ig = sigf(sl[j]);
            const float fg = sigf(sl[18 + j]);
            const float gg = tanhf_(sl[36 + j]);
            const float og = sigf(sl[54 + j]);
            c = fmaf(fg, c, ig * gg);
            const float hl = og * tanhf_(c);
            shl[j] = hl;
            v = hl * fw;
        }
        // warp reduction (lanes >=18 contribute 0)
        #pragma unroll
        for (int off = 16; off > 0; off >>= 1)
            v += __shfl_down_sync(0xffffffffu, v, off);

        // stage output; one STG.128 per 4 steps from lane 0
        ov[t & 3] = v + fb;
        if ((t & 3) == 3 && j == 0)
            *(float4*)(ob + (t - 3)) = make_float4(ov[0], ov[1], ov[2], ov[3]);

        xv = xnx;
        // no extra sync needed: next iteration's sx/shl writes are ordered
        // against this iteration's readers by syncs B..D.
    }
}

extern "C" void kernel_launch(void* const* d_in, const int* in_sizes, int n_in,
                              void* d_out, int out_size)
{
    (void)in_sizes; (void)n_in; (void)out_size;
    gru_lstm_fused<<<Bb, 32>>>(
        (const float*)d_in[0],
        (const float*)d_in[1], (const float*)d_in[2],
        (const float*)d_in[3], (const float*)d_in[4],
        (const float*)d_in[5], (const float*)d_in[6],
        (const float*)d_in[7], (const float*)d_in[8],
        (const float*)d_in[9], (const float*)d_in[10],
        (float*)d_out);
}

// round 8
// speedup vs baseline: 1.0232x; 1.0232x over previous
#include <cuda_runtime.h>

// GRU -> LSTM -> FC fused recurrent kernel, warp-specialized pipeline.
// B=1024 sequences, T=1024 steps, H=18.
// Block = 64 threads: warp 0 runs the GRU recurrence, warp 1 runs the
// LSTM+FC recurrence one timestep behind, consuming GRU outputs through
// a double-buffered shared slot. One bar.sync per pipeline stage.
// FC dot-products are deferred: per-step hl*fw is logged to a 32-step
// shared history; every 32 steps one amortized phase reduces 32 rows and
// emits a fully-coalesced 128B store (removes ~150cyc/step shuffle chain).

#define Hh 18
#define Tt 1024
#define Bb 1024

typedef unsigned long long ull;

__device__ __forceinline__ void fma2(ull &d, ull a, ull b) {
    asm("fma.rn.f32x2 %0, %1, %2, %0;" : "+l"(d) : "l"(a), "l"(b));
}
__device__ __forceinline__ float hadd2(ull v) {
    float lo, hi;
    asm("mov.b64 {%0,%1}, %2;" : "=f"(lo), "=f"(hi) : "l"(v));
    return lo + hi;
}
__device__ __forceinline__ float sigf(float x) {
    return __fdividef(1.f, 1.f + __expf(-x));
}
__device__ __forceinline__ float tanhf_(float x) {
    return 1.f - __fdividef(2.f, 1.f + __expf(2.f * x));
}
__device__ __forceinline__ void barrier64() {
    asm volatile("bar.sync 0, 64;" ::: "memory");
}

__global__ __launch_bounds__(64) void gru_lstm_pipe(
    const float* __restrict__ x,
    const float* __restrict__ gWih, const float* __restrict__ gWhh,
    const float* __restrict__ gbih, const float* __restrict__ gbhh,
    const float* __restrict__ lWih, const float* __restrict__ lWhh,
    const float* __restrict__ lbih, const float* __restrict__ lbhh,
    const float* __restrict__ fcW, const float* __restrict__ fcb,
    float* __restrict__ out)
{
    const int tid = threadIdx.x;
    const int w   = tid >> 5;     // 0 = GRU producer, 1 = LSTM consumer
    const int j   = tid & 31;
    const int b   = blockIdx.x;

    // shared state
    __shared__ __align__(16) float sx[Hh];       // x_t broadcast (warp 0)
    __shared__ __align__(16) float shg[Hh];      // GRU hidden broadcast (warp 0)
    __shared__ __align__(16) float sg[2][Hh];    // GRU output double buffer
    __shared__ __align__(16) float sxi[54];      // GRU input-proj rows
    __shared__ __align__(16) float shh[54];      // GRU hidden-proj rows
    __shared__ __align__(16) float shl[Hh];      // LSTM hidden broadcast (warp 1)
    __shared__ __align__(16) float sl[72];       // LSTM pre-activation rows
    __shared__ __align__(16) float hist[32][Hh]; // hl*fw history (warp 1)

    if (w == 0) {
        // ================= GRU producer warp =================
        // lane j (<27) owns rows 2j, 2j+1 of gWih/gWhh (9 f32x2 each)
        ull wgx[2][9], wgh[2][9];
        float bgx[2], bgh[2];
        if (j < 27) {
            #pragma unroll
            for (int r = 0; r < 2; r++) {
                const int row = 2 * j + r;
                const ull* pi = (const ull*)(gWih + row * Hh);
                const ull* ph = (const ull*)(gWhh + row * Hh);
                #pragma unroll
                for (int k = 0; k < 9; k++) { wgx[r][k] = pi[k]; wgh[r][k] = ph[k]; }
                bgx[r] = gbih[row];
                bgh[r] = gbhh[row];
            }
        }
        if (j < Hh) shg[j] = 0.f;
        float hg = 0.f;

        const float* xb = x + (size_t)b * Tt * Hh;
        float xv = (j < Hh) ? xb[j] : 0.f;   // prefetch x_0

        #pragma unroll 1
        for (int it = 0; it <= Tt; it++) {
            barrier64();
            if (it >= Tt) continue;
            const int t = it;

            if (j < Hh) sx[j] = xv;
            float xnx = 0.f;
            if (j < Hh && t + 1 < Tt) xnx = xb[(size_t)(t + 1) * Hh + j];
            __syncwarp();

            if (j < 27) {
                ull a0 = 0ULL, a1 = 0ULL, h0 = 0ULL, h1 = 0ULL;
                const ull* px = (const ull*)sx;
                const ull* ph = (const ull*)shg;
                #pragma unroll
                for (int k = 0; k < 9; k++) {
                    const ull xk = px[k], hk = ph[k];
                    fma2(a0, wgx[0][k], xk); fma2(h0, wgh[0][k], hk);
                    fma2(a1, wgx[1][k], xk); fma2(h1, wgh[1][k], hk);
                }
                sxi[2 * j]     = hadd2(a0) + bgx[0];
                sxi[2 * j + 1] = hadd2(a1) + bgx[1];
                shh[2 * j]     = hadd2(h0) + bgh[0];
                shh[2 * j + 1] = hadd2(h1) + bgh[1];
            }
            __syncwarp();

            if (j < Hh) {
                const float r = sigf(sxi[j]      + shh[j]);
                const float z = sigf(sxi[18 + j] + shh[18 + j]);
                const float n = tanhf_(fmaf(r, shh[36 + j], sxi[36 + j]));
                hg = fmaf(z, hg - n, n);          // (1-z)*n + z*h
                shg[j] = hg;
                sg[t & 1][j] = hg;                // publish to consumer
            }
            xv = xnx;
            // publication to warp 1 ordered by the barrier at loop top
        }
    } else {
        // ================= LSTM + FC consumer warp =================
        // lane j (<24) owns rows 3j..3j+2 of lWih/lWhh
        ull wlx[3][9], wlh[3][9];
        float bl[3];
        if (j < 24) {
            #pragma unroll
            for (int r = 0; r < 3; r++) {
                const int row = 3 * j + r;
                const ull* pi = (const ull*)(lWih + row * Hh);
                const ull* ph = (const ull*)(lWhh + row * Hh);
                #pragma unroll
                for (int k = 0; k < 9; k++) { wlx[r][k] = pi[k]; wlh[r][k] = ph[k]; }
                bl[r] = lbih[row] + lbhh[row];
            }
        }
        const float fw = (j < Hh) ? fcW[j] : 0.f;
        const float fb = fcb[0];
        if (j < Hh) shl[j] = 0.f;
        float c = 0.f;

        float* ob = out + (size_t)b * Tt;

        #pragma unroll 1
        for (int it = 0; it <= Tt; it++) {
            barrier64();
            if (it == 0) continue;
            const int t = it - 1;                 // consuming g_t

            if (j < 24) {
                const ull* pg = (const ull*)(sg[t & 1]);
                const ull* ph = (const ull*)shl;
                ull sa0 = 0ULL, sa1 = 0ULL, sa2 = 0ULL;
                ull sb0 = 0ULL, sb1 = 0ULL, sb2 = 0ULL;
                #pragma unroll
                for (int k = 0; k < 9; k++) {
                    const ull gk = pg[k], hk = ph[k];
                    fma2(sa0, wlx[0][k], gk); fma2(sb0, wlh[0][k], hk);
                    fma2(sa1, wlx[1][k], gk); fma2(sb1, wlh[1][k], hk);
                    fma2(sa2, wlx[2][k], gk); fma2(sb2, wlh[2][k], hk);
                }
                sl[3 * j]     = hadd2(sa0) + hadd2(sb0) + bl[0];
                sl[3 * j + 1] = hadd2(sa1) + hadd2(sb1) + bl[1];
                sl[3 * j + 2] = hadd2(sa2) + hadd2(sb2) + bl[2];
            }
            __syncwarp();

            if (j < Hh) {
                const float ig = sigf(sl[j]);
                const float fg = sigf(sl[18 + j]);
                const float gg = tanhf_(sl[36 + j]);
                const float og = sigf(sl[54 + j]);
                c = fmaf(fg, c, ig * gg);
                const float hl = og * tanhf_(c);
                shl[j] = hl;
                hist[t & 31][j] = hl * fw;        // deferred fc partial
            }

            // amortized fc reduction + coalesced store every 32 steps
            if ((t & 31) == 31) {
                __syncwarp();
                float v = fb;
                const float* hr = hist[j];        // lane j reduces step t-31+j
                #pragma unroll
                for (int k = 0; k < Hh; k++) v += hr[k];
                ob[t - 31 + j] = v;
            }
            // shl publication for next iter ordered by loop-top barrier
        }
    }
}

extern "C" void kernel_launch(void* const* d_in, const int* in_sizes, int n_in,
                              void* d_out, int out_size)
{
    (void)in_sizes; (void)n_in; (void)out_size;
    gru_lstm_pipe<<<Bb, 64>>>(
        (const float*)d_in[0],
        (const float*)d_in[1], (const float*)d_in[2],
        (const float*)d_in[3], (const float*)d_in[4],
        (const float*)d_in[5], (const float*)d_in[6],
        (const float*)d_in[7], (const float*)d_in[8],
        (const float*)d_in[9], (const float*)d_in[10],
        (float*)d_out);
}

// round 9
// speedup vs baseline: 1.1880x; 1.1611x over previous
#include <cuda_runtime.h>

// GRU -> LSTM -> FC fused recurrent kernel, warp-specialized pipeline,
// 2 sequences per block interleaved for ILP + single-wave residency.
// B=1024 sequences (512 blocks x 2), T=1024 steps, H=18.
// Block = 64 threads: warp 0 runs the GRU recurrence for both sequences,
// warp 1 runs the LSTM+FC recurrence one timestep behind. Weight registers
// are shared between the two sequences; their dependency chains interleave.

#define Hh 18
#define Tt 1024
#define NB 512   // blocks; 2 sequences each

typedef unsigned long long ull;

__device__ __forceinline__ void fma2(ull &d, ull a, ull b) {
    asm("fma.rn.f32x2 %0, %1, %2, %0;" : "+l"(d) : "l"(a), "l"(b));
}
__device__ __forceinline__ float hadd2(ull v) {
    float lo, hi;
    asm("mov.b64 {%0,%1}, %2;" : "=f"(lo), "=f"(hi) : "l"(v));
    return lo + hi;
}
__device__ __forceinline__ float sigf(float x) {
    return __fdividef(1.f, 1.f + __expf(-x));
}
__device__ __forceinline__ float tanhf_(float x) {
    return 1.f - __fdividef(2.f, 1.f + __expf(2.f * x));
}
__device__ __forceinline__ void barrier64() {
    asm volatile("bar.sync 0, 64;" ::: "memory");
}

__global__ __launch_bounds__(64) void gru_lstm_pipe2(
    const float* __restrict__ x,
    const float* __restrict__ gWih, const float* __restrict__ gWhh,
    const float* __restrict__ gbih, const float* __restrict__ gbhh,
    const float* __restrict__ lWih, const float* __restrict__ lWhh,
    const float* __restrict__ lbih, const float* __restrict__ lbhh,
    const float* __restrict__ fcW, const float* __restrict__ fcb,
    float* __restrict__ out)
{
    const int tid = threadIdx.x;
    const int w   = tid >> 5;     // 0 = GRU producer, 1 = LSTM consumer
    const int j   = tid & 31;
    const int b0  = 2 * blockIdx.x;   // sequences b0, b0+1

    // shared state (index [s] = sequence within block)
    __shared__ __align__(16) float sx[2][Hh];        // x_t
    __shared__ __align__(16) float shg[2][Hh];       // GRU hidden
    __shared__ __align__(16) float sg[2][2][Hh];     // [buf][seq] GRU out
    __shared__ __align__(16) float sxi[2][54];       // GRU input-proj rows
    __shared__ __align__(16) float shh[2][54];       // GRU hidden-proj rows
    __shared__ __align__(16) float shl[2][Hh];       // LSTM hidden
    __shared__ __align__(16) float sl[2][72];        // LSTM pre-activations
    __shared__ __align__(16) float hist[2][32][Hh];  // hl*fw history

    if (w == 0) {
        // ================= GRU producer warp (2 sequences) =================
        ull wgx[2][9], wgh[2][9];
        float bgx[2], bgh[2];
        if (j < 27) {
            #pragma unroll
            for (int r = 0; r < 2; r++) {
                const int row = 2 * j + r;
                const ull* pi = (const ull*)(gWih + row * Hh);
                const ull* ph = (const ull*)(gWhh + row * Hh);
                #pragma unroll
                for (int k = 0; k < 9; k++) { wgx[r][k] = pi[k]; wgh[r][k] = ph[k]; }
                bgx[r] = gbih[row];
                bgh[r] = gbhh[row];
            }
        }
        if (j < Hh) { shg[0][j] = 0.f; shg[1][j] = 0.f; }
        float hg0 = 0.f, hg1 = 0.f;

        const float* xb0 = x + (size_t)b0 * Tt * Hh;
        const float* xb1 = xb0 + (size_t)Tt * Hh;
        float xv0 = (j < Hh) ? xb0[j] : 0.f;
        float xv1 = (j < Hh) ? xb1[j] : 0.f;

        #pragma unroll 1
        for (int it = 0; it <= Tt; it++) {
            barrier64();
            if (it >= Tt) continue;
            const int t = it;

            if (j < Hh) { sx[0][j] = xv0; sx[1][j] = xv1; }
            float xn0 = 0.f, xn1 = 0.f;
            if (j < Hh && t + 1 < Tt) {
                xn0 = xb0[(size_t)(t + 1) * Hh + j];
                xn1 = xb1[(size_t)(t + 1) * Hh + j];
            }
            __syncwarp();

            if (j < 27) {
                // 8 independent accumulator chains (2 seqs x 2 rows x ih/hh)
                ull a00=0, a01=0, h00=0, h01=0, a10=0, a11=0, h10=0, h11=0;
                const ull* px0 = (const ull*)sx[0];
                const ull* px1 = (const ull*)sx[1];
                const ull* ph0 = (const ull*)shg[0];
                const ull* ph1 = (const ull*)shg[1];
                #pragma unroll
                for (int k = 0; k < 9; k++) {
                    const ull x0k = px0[k], h0k = ph0[k];
                    const ull x1k = px1[k], h1k = ph1[k];
                    fma2(a00, wgx[0][k], x0k); fma2(h00, wgh[0][k], h0k);
                    fma2(a01, wgx[1][k], x0k); fma2(h01, wgh[1][k], h0k);
                    fma2(a10, wgx[0][k], x1k); fma2(h10, wgh[0][k], h1k);
                    fma2(a11, wgx[1][k], x1k); fma2(h11, wgh[1][k], h1k);
                }
                sxi[0][2*j]   = hadd2(a00) + bgx[0];
                sxi[0][2*j+1] = hadd2(a01) + bgx[1];
                shh[0][2*j]   = hadd2(h00) + bgh[0];
                shh[0][2*j+1] = hadd2(h01) + bgh[1];
                sxi[1][2*j]   = hadd2(a10) + bgx[0];
                sxi[1][2*j+1] = hadd2(a11) + bgx[1];
                shh[1][2*j]   = hadd2(h10) + bgh[0];
                shh[1][2*j+1] = hadd2(h11) + bgh[1];
            }
            __syncwarp();

            if (j < Hh) {
                // two independent gate chains -> MUFU streams interleave
                const float r0 = sigf(sxi[0][j]      + shh[0][j]);
                const float r1 = sigf(sxi[1][j]      + shh[1][j]);
                const float z0 = sigf(sxi[0][18 + j] + shh[0][18 + j]);
                const float z1 = sigf(sxi[1][18 + j] + shh[1][18 + j]);
                const float n0 = tanhf_(fmaf(r0, shh[0][36 + j], sxi[0][36 + j]));
                const float n1 = tanhf_(fmaf(r1, shh[1][36 + j], sxi[1][36 + j]));
                hg0 = fmaf(z0, hg0 - n0, n0);
                hg1 = fmaf(z1, hg1 - n1, n1);
                shg[0][j] = hg0;  sg[t & 1][0][j] = hg0;
                shg[1][j] = hg1;  sg[t & 1][1][j] = hg1;
            }
            xv0 = xn0; xv1 = xn1;
        }
    } else {
        // ================= LSTM + FC consumer warp (2 sequences) ===========
        ull wlx[3][9], wlh[3][9];
        float bl[3];
        if (j < 24) {
            #pragma unroll
            for (int r = 0; r < 3; r++) {
                const int row = 3 * j + r;
                const ull* pi = (const ull*)(lWih + row * Hh);
                const ull* ph = (const ull*)(lWhh + row * Hh);
                #pragma unroll
                for (int k = 0; k < 9; k++) { wlx[r][k] = pi[k]; wlh[r][k] = ph[k]; }
                bl[r] = lbih[row] + lbhh[row];
            }
        }
        const float fw = (j < Hh) ? fcW[j] : 0.f;
        const float fb = fcb[0];
        if (j < Hh) { shl[0][j] = 0.f; shl[1][j] = 0.f; }
        float c0 = 0.f, c1 = 0.f;

        float* ob0 = out + (size_t)b0 * Tt;
        float* ob1 = ob0 + Tt;

        #pragma unroll 1
        for (int it = 0; it <= Tt; it++) {
            barrier64();
            if (it == 0) continue;
            const int t = it - 1;

            if (j < 24) {
                const ull* pg0 = (const ull*)(sg[t & 1][0]);
                const ull* pg1 = (const ull*)(sg[t & 1][1]);
                const ull* ph0 = (const ull*)shl[0];
                const ull* ph1 = (const ull*)shl[1];
                ull A0[3] = {0,0,0}, B0[3] = {0,0,0};
                ull A1[3] = {0,0,0}, B1[3] = {0,0,0};
                #pragma unroll
                for (int k = 0; k < 9; k++) {
                    const ull g0k = pg0[k], h0k = ph0[k];
                    const ull g1k = pg1[k], h1k = ph1[k];
                    #pragma unroll
                    for (int r = 0; r < 3; r++) {
                        fma2(A0[r], wlx[r][k], g0k); fma2(B0[r], wlh[r][k], h0k);
                        fma2(A1[r], wlx[r][k], g1k); fma2(B1[r], wlh[r][k], h1k);
                    }
                }
                #pragma unroll
                for (int r = 0; r < 3; r++) {
                    sl[0][3*j + r] = hadd2(A0[r]) + hadd2(B0[r]) + bl[r];
                    sl[1][3*j + r] = hadd2(A1[r]) + hadd2(B1[r]) + bl[r];
                }
            }
            __syncwarp();

            if (j < Hh) {
                const float i0 = sigf(sl[0][j]);
                const float i1 = sigf(sl[1][j]);
                const float f0 = sigf(sl[0][18 + j]);
                const float f1 = sigf(sl[1][18 + j]);
                const float g0 = tanhf_(sl[0][36 + j]);
                const float g1 = tanhf_(sl[1][36 + j]);
                const float o0 = sigf(sl[0][54 + j]);
                const float o1 = sigf(sl[1][54 + j]);
                c0 = fmaf(f0, c0, i0 * g0);
                c1 = fmaf(f1, c1, i1 * g1);
                const float hl0 = o0 * tanhf_(c0);
                const float hl1 = o1 * tanhf_(c1);
                shl[0][j] = hl0;  hist[0][t & 31][j] = hl0 * fw;
                shl[1][j] = hl1;  hist[1][t & 31][j] = hl1 * fw;
            }

            // amortized fc reduction + coalesced stores every 32 steps
            if ((t & 31) == 31) {
                __syncwarp();
                float v0 = fb, v1 = fb;
                const float* hr0 = hist[0][j];
                const float* hr1 = hist[1][j];
                #pragma unroll
                for (int k = 0; k < Hh; k++) { v0 += hr0[k]; v1 += hr1[k]; }
                ob0[t - 31 + j] = v0;
                ob1[t - 31 + j] = v1;
            }
        }
    }
}

extern "C" void kernel_launch(void* const* d_in, const int* in_sizes, int n_in,
                              void* d_out, int out_size)
{
    (void)in_sizes; (void)n_in; (void)out_size;
    gru_lstm_pipe2<<<NB, 64>>>(
        (const float*)d_in[0],
        (const float*)d_in[1], (const float*)d_in[2],
        (const float*)d_in[3], (const float*)d_in[4],
        (const float*)d_in[5], (const float*)d_in[6],
        (const float*)d_in[7], (const float*)d_in[8],
        (const float*)d_in[9], (const float*)d_in[10],
        (float*)d_out);
}

// round 11
// speedup vs baseline: 1.3302x; 1.1198x over previous
#include <cuda_runtime.h>

// GRU -> LSTM -> FC fused recurrent kernel, warp-specialized pipeline,
// 2 sequences per block interleaved, hardware-tanh gates (MUFU.TANH).
// B=1024 sequences (512 blocks x 2), T=1024 steps, H=18.
// Block = 64 threads: warp 0 runs the GRU recurrence for both sequences,
// warp 1 runs the LSTM+FC recurrence one timestep behind.

#define Hh 18
#define Tt 1024
#define NB 512   // blocks; 2 sequences each

typedef unsigned long long ull;

__device__ __forceinline__ void fma2(ull &d, ull a, ull b) {
    asm("fma.rn.f32x2 %0, %1, %2, %0;" : "+l"(d) : "l"(a), "l"(b));
}
__device__ __forceinline__ float hadd2(ull v) {
    float lo, hi;
    asm("mov.b64 {%0,%1}, %2;" : "=f"(lo), "=f"(hi) : "l"(v));
    return lo + hi;
}
// hardware tanh: single MUFU op
__device__ __forceinline__ float tanh_fast(float x) {
    float y;
    asm("tanh.approx.f32 %0, %1;" : "=f"(y) : "f"(x));
    return y;
}
// sigmoid via tanh identity: sigma(x) = 0.5 + 0.5*tanh(x/2)
__device__ __forceinline__ float sigf(float x) {
    return fmaf(0.5f, tanh_fast(0.5f * x), 0.5f);
}
__device__ __forceinline__ float tanhf_(float x) {
    return tanh_fast(x);
}
__device__ __forceinline__ void barrier64() {
    asm volatile("bar.sync 0, 64;" ::: "memory");
}

__global__ __launch_bounds__(64) void gru_lstm_pipe2t(
    const float* __restrict__ x,
    const float* __restrict__ gWih, const float* __restrict__ gWhh,
    const float* __restrict__ gbih, const float* __restrict__ gbhh,
    const float* __restrict__ lWih, const float* __restrict__ lWhh,
    const float* __restrict__ lbih, const float* __restrict__ lbhh,
    const float* __restrict__ fcW, const float* __restrict__ fcb,
    float* __restrict__ out)
{
    const int tid = threadIdx.x;
    const int w   = tid >> 5;     // 0 = GRU producer, 1 = LSTM consumer
    const int j   = tid & 31;
    const int b0  = 2 * blockIdx.x;   // sequences b0, b0+1

    // shared state (index [s] = sequence within block)
    __shared__ __align__(16) float sx[2][Hh];        // x_t
    __shared__ __align__(16) float shg[2][Hh];       // GRU hidden
    __shared__ __align__(16) float sg[2][2][Hh];     // [buf][seq] GRU out
    __shared__ __align__(16) float sxi[2][54];       // GRU input-proj rows
    __shared__ __align__(16) float shh[2][54];       // GRU hidden-proj rows
    __shared__ __align__(16) float shl[2][Hh];       // LSTM hidden
    __shared__ __align__(16) float sl[2][72];        // LSTM pre-activations
    __shared__ __align__(16) float hist[2][32][Hh];  // hl*fw history

    if (w == 0) {
        // ================= GRU producer warp (2 sequences) =================
        ull wgx[2][9], wgh[2][9];
        float bgx[2], bgh[2];
        if (j < 27) {
            #pragma unroll
            for (int r = 0; r < 2; r++) {
                const int row = 2 * j + r;
                const ull* pi = (const ull*)(gWih + row * Hh);
                const ull* ph = (const ull*)(gWhh + row * Hh);
                #pragma unroll
                for (int k = 0; k < 9; k++) { wgx[r][k] = pi[k]; wgh[r][k] = ph[k]; }
                bgx[r] = gbih[row];
                bgh[r] = gbhh[row];
            }
        }
        if (j < Hh) { shg[0][j] = 0.f; shg[1][j] = 0.f; }
        float hg0 = 0.f, hg1 = 0.f;

        const float* xb0 = x + (size_t)b0 * Tt * Hh;
        const float* xb1 = xb0 + (size_t)Tt * Hh;
        float xv0 = (j < Hh) ? xb0[j] : 0.f;
        float xv1 = (j < Hh) ? xb1[j] : 0.f;

        #pragma unroll 1
        for (int it = 0; it <= Tt; it++) {
            barrier64();
            if (it >= Tt) continue;
            const int t = it;

            if (j < Hh) { sx[0][j] = xv0; sx[1][j] = xv1; }
            float xn0 = 0.f, xn1 = 0.f;
            if (j < Hh && t + 1 < Tt) {
                xn0 = xb0[(size_t)(t + 1) * Hh + j];
                xn1 = xb1[(size_t)(t + 1) * Hh + j];
            }
            __syncwarp();

            if (j < 27) {
                // 8 independent accumulator chains (2 seqs x 2 rows x ih/hh)
                ull a00=0, a01=0, h00=0, h01=0, a10=0, a11=0, h10=0, h11=0;
                const ull* px0 = (const ull*)sx[0];
                const ull* px1 = (const ull*)sx[1];
                const ull* ph0 = (const ull*)shg[0];
                const ull* ph1 = (const ull*)shg[1];
                #pragma unroll
                for (int k = 0; k < 9; k++) {
                    const ull x0k = px0[k], h0k = ph0[k];
                    const ull x1k = px1[k], h1k = ph1[k];
                    fma2(a00, wgx[0][k], x0k); fma2(h00, wgh[0][k], h0k);
                    fma2(a01, wgx[1][k], x0k); fma2(h01, wgh[1][k], h0k);
                    fma2(a10, wgx[0][k], x1k); fma2(h10, wgh[0][k], h1k);
                    fma2(a11, wgx[1][k], x1k); fma2(h11, wgh[1][k], h1k);
                }
                sxi[0][2*j]   = hadd2(a00) + bgx[0];
                sxi[0][2*j+1] = hadd2(a01) + bgx[1];
                shh[0][2*j]   = hadd2(h00) + bgh[0];
                shh[0][2*j+1] = hadd2(h01) + bgh[1];
                sxi[1][2*j]   = hadd2(a10) + bgx[0];
                sxi[1][2*j+1] = hadd2(a11) + bgx[1];
                shh[1][2*j]   = hadd2(h10) + bgh[0];
                shh[1][2*j+1] = hadd2(h11) + bgh[1];
            }
            __syncwarp();

            if (j < Hh) {
                // two independent gate chains; 1 MUFU per gate
                const float r0 = sigf(sxi[0][j]      + shh[0][j]);
                const float r1 = sigf(sxi[1][j]      + shh[1][j]);
                const float z0 = sigf(sxi[0][18 + j] + shh[0][18 + j]);
                const float z1 = sigf(sxi[1][18 + j] + shh[1][18 + j]);
                const float n0 = tanhf_(fmaf(r0, shh[0][36 + j], sxi[0][36 + j]));
                const float n1 = tanhf_(fmaf(r1, shh[1][36 + j], sxi[1][36 + j]));
                hg0 = fmaf(z0, hg0 - n0, n0);
                hg1 = fmaf(z1, hg1 - n1, n1);
                shg[0][j] = hg0;  sg[t & 1][0][j] = hg0;
                shg[1][j] = hg1;  sg[t & 1][1][j] = hg1;
            }
            xv0 = xn0; xv1 = xn1;
        }
    } else {
        // ================= LSTM + FC consumer warp (2 sequences) ===========
        ull wlx[3][9], wlh[3][9];
        float bl[3];
        if (j < 24) {
            #pragma unroll
            for (int r = 0; r < 3; r++) {
                const int row = 3 * j + r;
                const ull* pi = (const ull*)(lWih + row * Hh);
                const ull* ph = (const ull*)(lWhh + row * Hh);
                #pragma unroll
                for (int k = 0; k < 9; k++) { wlx[r][k] = pi[k]; wlh[r][k] = ph[k]; }
                bl[r] = lbih[row] + lbhh[row];
            }
        }
        const float fw = (j < Hh) ? fcW[j] : 0.f;
        const float fb = fcb[0];
        if (j < Hh) { shl[0][j] = 0.f; shl[1][j] = 0.f; }
        float c0 = 0.f, c1 = 0.f;

        float* ob0 = out + (size_t)b0 * Tt;
        float* ob1 = ob0 + Tt;

        #pragma unroll 1
        for (int it = 0; it <= Tt; it++) {
            barrier64();
            if (it == 0) continue;
            const int t = it - 1;

            if (j < 24) {
                const ull* pg0 = (const ull*)(sg[t & 1][0]);
                const ull* pg1 = (const ull*)(sg[t & 1][1]);
                const ull* ph0 = (const ull*)shl[0];
                const ull* ph1 = (const ull*)shl[1];
                ull A0[3] = {0,0,0}, B0[3] = {0,0,0};
                ull A1[3] = {0,0,0}, B1[3] = {0,0,0};
                #pragma unroll
                for (int k = 0; k < 9; k++) {
                    const ull g0k = pg0[k], h0k = ph0[k];
                    const ull g1k = pg1[k], h1k = ph1[k];
                    #pragma unroll
                    for (int r = 0; r < 3; r++) {
                        fma2(A0[r], wlx[r][k], g0k); fma2(B0[r], wlh[r][k], h0k);
                        fma2(A1[r], wlx[r][k], g1k); fma2(B1[r], wlh[r][k], h1k);
                    }
                }
                #pragma unroll
                for (int r = 0; r < 3; r++) {
                    sl[0][3*j + r] = hadd2(A0[r]) + hadd2(B0[r]) + bl[r];
                    sl[1][3*j + r] = hadd2(A1[r]) + hadd2(B1[r]) + bl[r];
                }
            }
            __syncwarp();

            if (j < Hh) {
                const float i0 = sigf(sl[0][j]);
                const float i1 = sigf(sl[1][j]);
                const float f0 = sigf(sl[0][18 + j]);
                const float f1 = sigf(sl[1][18 + j]);
                const float g0 = tanhf_(sl[0][36 + j]);
                const float g1 = tanhf_(sl[1][36 + j]);
                const float o0 = sigf(sl[0][54 + j]);
                const float o1 = sigf(sl[1][54 + j]);
                c0 = fmaf(f0, c0, i0 * g0);
                c1 = fmaf(f1, c1, i1 * g1);
                const float hl0 = o0 * tanhf_(c0);
                const float hl1 = o1 * tanhf_(c1);
                shl[0][j] = hl0;  hist[0][t & 31][j] = hl0 * fw;
                shl[1][j] = hl1;  hist[1][t & 31][j] = hl1 * fw;
            }

            // amortized fc reduction + coalesced stores every 32 steps
            if ((t & 31) == 31) {
                __syncwarp();
                float v0 = fb, v1 = fb;
                const float* hr0 = hist[0][j];
                const float* hr1 = hist[1][j];
                #pragma unroll
                for (int k = 0; k < Hh; k++) { v0 += hr0[k]; v1 += hr1[k]; }
                ob0[t - 31 + j] = v0;
                ob1[t - 31 + j] = v1;
            }
        }
    }
}

extern "C" void kernel_launch(void* const* d_in, const int* in_sizes, int n_in,
                              void* d_out, int out_size)
{
    (void)in_sizes; (void)n_in; (void)out_size;
    gru_lstm_pipe2t<<<NB, 64>>>(
        (const float*)d_in[0],
        (const float*)d_in[1], (const float*)d_in[2],
        (const float*)d_in[3], (const float*)d_in[4],
        (const float*)d_in[5], (const float*)d_in[6],
        (const float*)d_in[7], (const float*)d_in[8],
        (const float*)d_in[9], (const float*)d_in[10],
        (float*)d_out);
}